// round 14
// baseline (speedup 1.0000x reference)
#include <cuda_runtime.h>

// CoupledClustersLossV2 — 512 concurrent streams (128-thr CTAs, occ 4).
// embeddings: [256 cls][2 pos/neg][32 samples][2048] fp32 = 128 MB.
// ||x - a||^2 = ||x||^2 - (x·s)/16 + ||s||^2/1024,  s = sum of 32 pos rows.
//
// R10/R13 evidence: kernel time invariant under SMEM-traffic halving; BW
// fits per-CTA rate cap ~19.8 GB/s x 256 streams = 5.1 TB/s. This round
// doubles stream count: 512 CTAs (class-half each: 1024 cols, 8 static
// chunks) x 128 threads at occupancy 4 — still a single wave (<=592 slots),
// aggregate demand ~10 TB/s > memory-system cap, so BW saturates and
// equal-share scheduling makes CTA-count imbalance irrelevant.
// Machinery proven in R10-R13: self-visible cp.async pos tiles (no tile
// barrier), 3 stages, neg rows direct __ldcg, ONE barrier per chunk
// (column-sum exchange), single end-of-CTA flush, epoch-counter combine
// (replay-safe), fixed-order sums (deterministic).

#define NCLS     256
#define NS       32
#define DIM      2048
#define CHUNK    128
#define THREADS  128                          // 4 warps
#define GRID     (NCLS * 2)                   // 512: class-half per CTA
#define NCH      8                            // 1024 cols / 128
#define NSTAGE   3
#define TILE_F4  1024                         // pos tile: 32 rows x 32 f4 = 16KB
#define SMEM_BYTES (NSTAGE * TILE_F4 * 16 + 2 * 4 * CHUNK * 4)   // 53248
#define ROW_F4   (DIM / 4)                    // 512
#define MARGIN   0.3f

// per-(class, half) row partials: 0=||pos||^2 1=pos·s 2=||neg||^2 3=neg·s
__device__ float        g_scratch[NCLS][2][4][NS];
__device__ unsigned int g_done[NCLS];         // epoch counters (never reset)
__device__ float        g_class_loss[NCLS];
__device__ unsigned int g_cls_done;           // epoch counter (never reset)

__device__ __forceinline__ float dot4(float4 a, float4 b) {
    return fmaf(a.x, b.x, fmaf(a.y, b.y, fmaf(a.z, b.z, a.w * b.w)));
}
__device__ __forceinline__ float wsum(float v) {
#pragma unroll
    for (int o = 16; o > 0; o >>= 1) v += __shfl_xor_sync(0xffffffffu, v, o);
    return v;
}
__device__ __forceinline__ void cp_async16(unsigned smem_dst, const float4* gsrc) {
    asm volatile("cp.async.cg.shared.global [%0], [%1], 16;\n"
                 :: "r"(smem_dst), "l"(gsrc));
}

__global__ __launch_bounds__(THREADS, 4)
void ccl_kernel(const float* __restrict__ emb, float* __restrict__ out)
{
    extern __shared__ float4 sh4[];                       // [NSTAGE][TILE_F4] pos tiles
    float* spart = (float*)(sh4 + NSTAGE * TILE_F4);      // [2][4][CHUNK]

    const int bid  = blockIdx.x;
    const int cls  = bid >> 1;
    const int part = bid & 1;
    const int tid  = threadIdx.x;
    const int warp = tid >> 5;                            // 0..3
    const int lane = tid & 31;

    // Thread's rows: pos {warp+4i}, neg {32+warp+4i}, i=0..7; f4-col = lane.
    const unsigned slot0  = (unsigned)((warp * 32 + lane) * 16);
    const unsigned smbase = (unsigned)__cvta_generic_to_shared(sh4);
    const float4*  gbase  = (const float4*)emb + ((size_t)cls << 15)   // 2*NS*DIM/4
                            + (part << 8)                              // half: 1024 cols
                            + (size_t)warp * ROW_F4 + lane;

    // Issue pos chunk c: this thread's own 8 slots (rows step 4 = 2048B in tile).
    auto issue = [&](int c) {
        const float4*  g  = gbase + (c << 5);             // c * CHUNK/4
        const unsigned sb = smbase + (unsigned)(c % NSTAGE) * (TILE_F4 * 16);
#pragma unroll
        for (int i = 0; i < 8; ++i)
            cp_async16(sb + slot0 + i * 2048u, g + (size_t)(i * 4) * ROW_F4);
        asm volatile("cp.async.commit_group;\n" ::);
    };

    issue(0); issue(1); issue(2);

    float pn[8], tp[8], nn[8], tn[8];
#pragma unroll
    for (int i = 0; i < 8; ++i) { pn[i] = tp[i] = nn[i] = tn[i] = 0.f; }

#pragma unroll
    for (int c = 0; c < NCH; ++c) {
        const int sb = c & 1;
        const float4* tile = sh4 + (c % NSTAGE) * TILE_F4;

        // Neg rows straight from GMEM (warp = 512B contiguous). Issued before
        // the wait so DRAM latency hides under it. .cg = streaming, no L1.
        float4 n[8];
#pragma unroll
        for (int i = 0; i < 8; ++i)
            n[i] = __ldcg(gbase + (c << 5) + (size_t)(NS + i * 4) * ROW_F4);

        // Self-visibility: we read only our own cp.async copies -> no barrier.
        if (c + 2 < NCH)      asm volatile("cp.async.wait_group 2;\n" ::);
        else if (c + 1 < NCH) asm volatile("cp.async.wait_group 1;\n" ::);
        else                  asm volatile("cp.async.wait_group 0;\n" ::);

        float4 p[8];
#pragma unroll
        for (int i = 0; i < 8; ++i)
            p[i] = tile[(warp + i * 4) * 32 + lane];

        // Norms + per-warp column-sum partial (8 rows per warp).
#pragma unroll
        for (int i = 0; i < 8; ++i) {
            pn[i] += dot4(p[i], p[i]);
            nn[i] += dot4(n[i], n[i]);
        }
        float4 spv;
        spv.x = ((p[0].x + p[1].x) + (p[2].x + p[3].x)) + ((p[4].x + p[5].x) + (p[6].x + p[7].x));
        spv.y = ((p[0].y + p[1].y) + (p[2].y + p[3].y)) + ((p[4].y + p[5].y) + (p[6].y + p[7].y));
        spv.z = ((p[0].z + p[1].z) + (p[2].z + p[3].z)) + ((p[4].z + p[5].z) + (p[6].z + p[7].z));
        spv.w = ((p[0].w + p[1].w) + (p[2].w + p[3].w)) + ((p[4].w + p[5].w) + (p[6].w + p[7].w));
        *(float4*)&spart[(sb * 4 + warp) * CHUNK + lane * 4] = spv;

        __syncthreads();   // the ONLY per-chunk barrier (colsum exchange)

        if (c + 3 < NCH) issue(c + 3);   // refill our own consumed slots

        // Full column sums: 4 warp partials.
        float4 sc = *(const float4*)&spart[(sb * 4 + 0) * CHUNK + lane * 4];
#pragma unroll
        for (int w = 1; w < 4; ++w) {
            float4 t = *(const float4*)&spart[(sb * 4 + w) * CHUNK + lane * 4];
            sc.x += t.x; sc.y += t.y; sc.z += t.z; sc.w += t.w;
        }
#pragma unroll
        for (int i = 0; i < 8; ++i) {
            tp[i] += dot4(p[i], sc);
            tn[i] += dot4(n[i], sc);
        }
        // spart[sb] rewritten at chunk c+2, after barrier c+1 -> safe.
    }

    // ---- single end-of-CTA flush: publish this half's row partials ----
#pragma unroll
    for (int i = 0; i < 8; ++i) {
        const float a = wsum(pn[i]);
        const float b = wsum(tp[i]);
        const float d = wsum(nn[i]);
        const float e = wsum(tn[i]);
        if (lane == 0) {
            const int row = warp + i * 4;
            g_scratch[cls][part][0][row] = a;
            g_scratch[cls][part][1][row] = b;
            g_scratch[cls][part][2][row] = d;
            g_scratch[cls][part][3][row] = e;
        }
    }
    __syncthreads();       // all warps' STGs issued before the count

    if (warp != 0) return;

    unsigned fin = 0;
    if (lane == 0) {
        __threadfence();                       // publish scratch
        const unsigned old = atomicAdd(&g_done[cls], 1u);
        fin = old & 1u;                        // exp = 2 contributors
    }
    fin = __shfl_sync(0xffffffffu, fin, 0);
    if (!fin) return;

    // ---- per-class finisher (last-arriving half; fixed-order sums) ----
    __threadfence();
    const float fpn = __ldcg(&g_scratch[cls][0][0][lane]) + __ldcg(&g_scratch[cls][1][0][lane]);
    const float ftp = __ldcg(&g_scratch[cls][0][1][lane]) + __ldcg(&g_scratch[cls][1][1][lane]);
    const float fnn = __ldcg(&g_scratch[cls][0][2][lane]) + __ldcg(&g_scratch[cls][1][2][lane]);
    const float ftn = __ldcg(&g_scratch[cls][0][3][lane]) + __ldcg(&g_scratch[cls][1][3][lane]);

    const float ssum  = wsum(ftp);                 // ||s||^2 = sum_i pos_i·s
    const float anorm = ssum * (1.0f / 1024.0f);   // ||s||^2 / 32^2
    const float ap2   = fpn - ftp * (1.0f / 16.0f) + anorm;
    const float nd2   = fnn - ftn * (1.0f / 16.0f) + anorm;

    float mn = nd2;
#pragma unroll
    for (int o = 16; o > 0; o >>= 1)
        mn = fminf(mn, __shfl_xor_sync(0xffffffffu, mn, o));
    const float an = sqrtf(fmaxf(mn, 0.f));

    float t = fmaxf(sqrtf(fmaxf(ap2, 0.f)) - an + MARGIN, 0.f);
    const float term = wsum(t * t);

    unsigned old2 = 0;
    if (lane == 0) {
        g_class_loss[cls] = term;
        __threadfence();
        old2 = atomicAdd(&g_cls_done, 1u);
    }
    old2 = __shfl_sync(0xffffffffu, old2, 0);
    if ((old2 & (NCLS - 1u)) != (NCLS - 1u)) return;

    // ---- global finisher: fixed-order mean over 256 class losses ----
    __threadfence();
    float v = 0.f;
#pragma unroll
    for (int q = 0; q < NCLS / 32; ++q)
        v += __ldcg(&g_class_loss[q * 32 + lane]);
    v = wsum(v);
    if (lane == 0) out[0] = v * (1.0f / (float)NCLS);
}

extern "C" void kernel_launch(void* const* d_in, const int* in_sizes, int n_in,
                              void* d_out, int out_size)
{
    (void)in_sizes; (void)n_in; (void)out_size;
    const float* emb = (const float*)d_in[0];   // [16384, 2048] fp32
    // d_in[1] (target) is unused by the reference computation.
    cudaFuncSetAttribute(ccl_kernel, cudaFuncAttributeMaxDynamicSharedMemorySize,
                         SMEM_BYTES);
    ccl_kernel<<<GRID, THREADS, SMEM_BYTES>>>(emb, (float*)d_out);
}

// round 15
// speedup vs baseline: 1.1509x; 1.1509x over previous
#include <cuda_runtime.h>

// CoupledClustersLossV2 — CHUNK=256: half the barriers per byte. HBM-bound.
// embeddings: [256 cls][2 pos/neg][32 samples][2048] fp32 = 128 MB.
// ||x - a||^2 = ||x||^2 - (x·s)/16 + ||s||^2/1024,  s = sum of 32 pos rows.
//
// R13/R14 evidence: busy SMs stream at 38.6 GB/s vs 54 available -> SM-limited
// by a ~0.26us fixed serial chain per chunk (wait->colsum->BAR->gather), not
// by BW, imbalance, or stream count. This round doubles bytes per barrier
// (CHUNK=256, 8 chunks instead of 16). Register blowup avoided by never
// holding p across the barrier: phase1 streams p transiently (pn + colsum
// partials), phase3 RE-READS p from the SMEM tile (SMEM throughput proven
// non-binding in R13). neg rows stay direct __ldcg (n[8] register-resident).
// Proven skeleton: 256 CTAs x 256 thr (one class each), self-visible
// cp.async (thread copies exactly the slots it reads -> no tile barrier),
// 2 stages, ONE barrier per chunk, single end-of-CTA flush, epoch-counter
// finishers (replay-safe), fixed-order sums (deterministic).

#define NCLS     256
#define NS       32
#define DIM      2048
#define CHUNK    256                          // columns per chunk
#define THREADS  256
#define NCH      8                            // DIM / CHUNK, compile-time
#define TILE_F4  2048                         // pos tile: 32 rows x 64 f4 = 32KB
#define SPART_F4 (8 * 64)                     // 8 warps x 64 f4 cols
#define SMEM_BYTES (2 * TILE_F4 * 16 + 2 * SPART_F4 * 16)   // 81920
#define ROW_F4   (DIM / 4)                    // 512
#define MARGIN   0.3f

__device__ float        g_class_loss[NCLS];
__device__ unsigned int g_cls_done;           // epoch counter (never reset)

__device__ __forceinline__ float dot4(float4 a, float4 b) {
    return fmaf(a.x, b.x, fmaf(a.y, b.y, fmaf(a.z, b.z, a.w * b.w)));
}
__device__ __forceinline__ float wsum(float v) {
#pragma unroll
    for (int o = 16; o > 0; o >>= 1) v += __shfl_xor_sync(0xffffffffu, v, o);
    return v;
}
__device__ __forceinline__ void cp_async16(unsigned smem_dst, const float4* gsrc) {
    asm volatile("cp.async.cg.shared.global [%0], [%1], 16;\n"
                 :: "r"(smem_dst), "l"(gsrc));
}
__device__ __forceinline__ void f4add(float4& a, float4 b) {
    a.x += b.x; a.y += b.y; a.z += b.z; a.w += b.w;
}

__global__ __launch_bounds__(THREADS, 2)
void ccl_kernel(const float* __restrict__ emb, float* __restrict__ out)
{
    extern __shared__ float4 sh4[];                       // [2][TILE_F4] pos tiles
    float4* spart = sh4 + 2 * TILE_F4;                    // [2][8][64] f4 partials
    __shared__ float red[4][NS];                          // flush staging

    const int cls  = blockIdx.x;
    const int tid  = threadIdx.x;
    const int warp = tid >> 5;
    const int lane = tid & 31;

    // Thread's tile slots: pos rows warp+8i (i=0..3), f4-cols lane and lane+32.
    // Tile layout: row r at r*64 f4 (1024B); row step 8 -> 8192B.
    const unsigned slot0  = (unsigned)((warp * 64 + lane) * 16);
    const unsigned smbase = (unsigned)__cvta_generic_to_shared(sh4);
    const float4*  gbase  = (const float4*)emb + ((size_t)cls << 15)   // 2*NS*DIM/4
                            + (size_t)warp * ROW_F4 + lane;

    // Issue pos chunk c into stage (c&1): this thread's own 8 slots.
    auto issue = [&](int c) {
        const float4*  g  = gbase + (c << 6);             // c * CHUNK/4
        const unsigned sb = smbase + (unsigned)(c & 1) * (TILE_F4 * 16);
#pragma unroll
        for (int i = 0; i < 4; ++i) {
            cp_async16(sb + slot0 + i * 8192u,        g + (size_t)(i * 8) * ROW_F4);
            cp_async16(sb + slot0 + 512u + i * 8192u, g + (size_t)(i * 8) * ROW_F4 + 32);
        }
        asm volatile("cp.async.commit_group;\n" ::);
    };

    issue(0); issue(1);

    float pn[4] = {0.f,0.f,0.f,0.f};
    float tp[4] = {0.f,0.f,0.f,0.f};
    float nn[4] = {0.f,0.f,0.f,0.f};
    float tn[4] = {0.f,0.f,0.f,0.f};

#pragma unroll
    for (int c = 0; c < NCH; ++c) {
        const int sb = c & 1;
        const float4* tile = sh4 + sb * TILE_F4;

        // Neg rows straight from GMEM (coalesced), issued before the wait so
        // DRAM latency hides under it. n[8]: row i -> n[2i] (col lane),
        // n[2i+1] (col lane+32). .cg = streaming, no L1 pollution.
        float4 n[8];
#pragma unroll
        for (int i = 0; i < 4; ++i) {
            n[2*i]   = __ldcg(gbase + (c << 6) + (size_t)(NS + i * 8) * ROW_F4);
            n[2*i+1] = __ldcg(gbase + (c << 6) + (size_t)(NS + i * 8) * ROW_F4 + 32);
        }

        // Self-visibility: we read only our own cp.async copies -> no barrier.
        if (c + 1 < NCH) asm volatile("cp.async.wait_group 1;\n" ::);
        else             asm volatile("cp.async.wait_group 0;\n" ::);

        // Phase 1: stream p transiently -> pn + per-warp colsum partials.
        float4 sp0 = {0.f,0.f,0.f,0.f}, sp1 = {0.f,0.f,0.f,0.f};
#pragma unroll
        for (int i = 0; i < 4; ++i) {
            const float4 p0 = tile[(warp + i * 8) * 64 + lane];
            const float4 p1 = tile[(warp + i * 8) * 64 + lane + 32];
            pn[i] += dot4(p0, p0) + dot4(p1, p1);
            f4add(sp0, p0); f4add(sp1, p1);
            nn[i] += dot4(n[2*i], n[2*i]) + dot4(n[2*i+1], n[2*i+1]);
        }
        spart[(sb * 8 + warp) * 64 + lane]      = sp0;
        spart[(sb * 8 + warp) * 64 + lane + 32] = sp1;

        __syncthreads();   // the ONLY per-chunk barrier (colsum exchange)

        // Phase 3: gather full column sums, re-read p from tile, accumulate.
        float4 sc0 = spart[(sb * 8 + 0) * 64 + lane];
        float4 sc1 = spart[(sb * 8 + 0) * 64 + lane + 32];
#pragma unroll
        for (int w = 1; w < 8; ++w) {
            f4add(sc0, spart[(sb * 8 + w) * 64 + lane]);
            f4add(sc1, spart[(sb * 8 + w) * 64 + lane + 32]);
        }
#pragma unroll
        for (int i = 0; i < 4; ++i) {
            const float4 p0 = tile[(warp + i * 8) * 64 + lane];
            const float4 p1 = tile[(warp + i * 8) * 64 + lane + 32];
            tp[i] += dot4(p0, sc0) + dot4(p1, sc1);
            tn[i] += dot4(n[2*i], sc0) + dot4(n[2*i+1], sc1);
        }

        // Refill this stage (our own, now fully re-read slots).
        if (c + 2 < NCH) issue(c + 2);
        // spart[sb] rewritten at chunk c+2 phase1, i.e. after barrier c+1 -> safe.
    }

    // ---- single end-of-CTA flush: class loss computed entirely in-CTA ----
#pragma unroll
    for (int i = 0; i < 4; ++i) {
        const float a = wsum(pn[i]);
        const float b = wsum(tp[i]);
        const float d = wsum(nn[i]);
        const float e = wsum(tn[i]);
        if (lane == 0) {
            const int row = warp + i * 8;
            red[0][row] = a;
            red[1][row] = b;
            red[2][row] = d;
            red[3][row] = e;
        }
    }
    __syncthreads();

    if (warp == 0) {
        const float pnv = red[0][lane];
        const float tpv = red[1][lane];
        const float nnv = red[2][lane];
        const float tnv = red[3][lane];

        const float ssum  = wsum(tpv);                 // ||s||^2
        const float anorm = ssum * (1.0f / 1024.0f);   // ||s||^2 / 32^2
        const float ap2   = pnv - tpv * (1.0f / 16.0f) + anorm;
        const float nd2   = nnv - tnv * (1.0f / 16.0f) + anorm;

        float mn = nd2;
#pragma unroll
        for (int o = 16; o > 0; o >>= 1)
            mn = fminf(mn, __shfl_xor_sync(0xffffffffu, mn, o));
        const float an = sqrtf(fmaxf(mn, 0.f));

        float t = fmaxf(sqrtf(fmaxf(ap2, 0.f)) - an + MARGIN, 0.f);
        const float term = wsum(t * t);

        unsigned old = 0;
        if (lane == 0) {
            g_class_loss[cls] = term;
            __threadfence();
            old = atomicAdd(&g_cls_done, 1u);
        }
        old = __shfl_sync(0xffffffffu, old, 0);
        if ((old & (NCLS - 1u)) == (NCLS - 1u)) {
            // ---- global finisher: fixed-order mean over 256 class losses ----
            __threadfence();
            float v = 0.f;
#pragma unroll
            for (int q = 0; q < NCLS / 32; ++q)
                v += __ldcg(&g_class_loss[q * 32 + lane]);
            v = wsum(v);
            if (lane == 0) out[0] = v * (1.0f / (float)NCLS);
        }
    }
}

extern "C" void kernel_launch(void* const* d_in, const int* in_sizes, int n_in,
                              void* d_out, int out_size)
{
    (void)in_sizes; (void)n_in; (void)out_size;
    const float* emb = (const float*)d_in[0];   // [16384, 2048] fp32
    // d_in[1] (target) is unused by the reference computation.
    cudaFuncSetAttribute(ccl_kernel, cudaFuncAttributeMaxDynamicSharedMemorySize,
                         SMEM_BYTES);
    ccl_kernel<<<NCLS, THREADS, SMEM_BYTES>>>(emb, (float*)d_out);
}